// round 14
// baseline (speedup 1.0000x reference)
#include <cuda_runtime.h>
#include <cuda_bf16.h>
#include <cuda_fp16.h>
#include <math.h>
#include <stdint.h>

#define Bsz 64
#define Lsz 512
#define DIN 1024
#define Hsz 1024
#define Gsz 4096
#define ML (Bsz*Lsz)            // 32768
#define OUTN ((size_t)Bsz*Lsz*Hsz) // 33554432

// ---------------- scratch (static device allocations) ----------------
__device__ float g_xproj[(size_t)ML*Gsz];                 // 512 MB
__device__ __half g_xh[(size_t)ML*DIN];        // x in fp16
__device__ __half g_wxhi_h[(size_t)Gsz*DIN];   // Wx fp16 (1-term)
__device__ __half g_whhi_h[(size_t)Gsz*Hsz];   // fp16(512*Wh) (1-term)
__device__ __half g_hh3[3][Bsz*Hsz];           // h, fp16, triple-buffered
__device__ unsigned g_rc[8];    // per-K-region step counters

// ---------------- helpers ----------------
__device__ __forceinline__ void mma16816h(float* c, const unsigned* a, const unsigned* b) {
    asm volatile(
        "mma.sync.aligned.m16n8k16.row.col.f32.f16.f16.f32 "
        "{%0,%1,%2,%3}, {%4,%5,%6,%7}, {%8,%9}, {%0,%1,%2,%3};\n"
        : "+f"(c[0]), "+f"(c[1]), "+f"(c[2]), "+f"(c[3])
        : "r"(a[0]), "r"(a[1]), "r"(a[2]), "r"(a[3]), "r"(b[0]), "r"(b[1]));
}

__device__ __forceinline__ void ldsm_x4(unsigned* r, const void* p) {
    unsigned a = (unsigned)__cvta_generic_to_shared(p);
    asm volatile("ldmatrix.sync.aligned.m8n8.x4.shared.b16 {%0,%1,%2,%3}, [%4];\n"
        : "=r"(r[0]), "=r"(r[1]), "=r"(r[2]), "=r"(r[3]) : "r"(a));
}

__device__ __forceinline__ void cp16(void* dst, const void* src) {
    unsigned d = (unsigned)__cvta_generic_to_shared(dst);
    asm volatile("cp.async.cg.shared.global [%0], [%1], 16;\n" :: "r"(d), "l"(src));
}
__device__ __forceinline__ void cp_commit() { asm volatile("cp.async.commit_group;\n"); }
__device__ __forceinline__ void cp_wait2()  { asm volatile("cp.async.wait_group 2;\n"); }
__device__ __forceinline__ void cp_wait1()  { asm volatile("cp.async.wait_group 1;\n"); }
__device__ __forceinline__ void cp_wait0()  { asm volatile("cp.async.wait_group 0;\n"); }

__device__ __forceinline__ void red_release(unsigned* p, unsigned v) {
    asm volatile("red.release.gpu.global.add.u32 [%0], %1;" :: "l"(p), "r"(v) : "memory");
}

__device__ __forceinline__ float sigmoidf_(float x) {
    return __fdividef(1.0f, 1.0f + __expf(-x));
}
__device__ __forceinline__ float tanhf_(float x) {
    return __fdividef(2.0f, 1.0f + __expf(-2.0f * x)) - 1.0f;
}

// ---------------- split kernels ----------------
__global__ void split_x_kernel(const float* __restrict__ x) {
    size_t stride = (size_t)gridDim.x * blockDim.x;
    for (size_t i = (size_t)blockIdx.x * blockDim.x + threadIdx.x;
         i < (size_t)ML * DIN; i += stride) {
        g_xh[i] = __float2half(x[i]);
    }
}

__global__ void split_w_kernel(const float* __restrict__ W) {
    size_t stride = (size_t)gridDim.x * blockDim.x;
    for (size_t i = (size_t)blockIdx.x * blockDim.x + threadIdx.x;
         i < (size_t)Gsz * (Hsz + DIN); i += stride) {
        int r = (int)(i >> 11);
        int c = (int)(i & 2047);
        float v = W[i];
        size_t d = (size_t)r * 1024 + (c & 1023);
        if (c < 1024) {
            g_whhi_h[d] = __float2half(v * 512.0f);
        } else {
            g_wxhi_h[d] = __float2half(v);
        }
    }
}

__global__ void init_kernel() {
    int i = blockIdx.x * blockDim.x + threadIdx.x;
    if (i < 8) g_rc[i] = 0;
    if (i < Bsz * Hsz) g_hh3[0][i] = __float2half(0.0f);
}

// ---------------- phase 1: x_proj GEMM (R13 verbatim: 4-stage ring, 1 sync/iter) ----------------
#define P1_BM 128
#define P1_BN 128
#define P1_BK 32
#define P1_ROW 40           // 32 + 8 pad
#define P1_PLANE (P1_BM * P1_ROW)          // elems per stage per matrix (5120)
#define P1_SMEM ((size_t)8 * P1_PLANE * 2) // 4 stages * (A+B) * fp16 = 81920 B

__global__ __launch_bounds__(256, 2) void xproj_kernel(const float* __restrict__ bias) {
    extern __shared__ __half xsm[];
    __half* As = xsm;                      // [4][128][40]
    __half* Bs = xsm + 4 * P1_PLANE;       // [4][128][40]

    const int tid = threadIdx.x;
    const int wid = tid >> 5, lane = tid & 31;
    const int wm = wid & 3;
    const int wn = wid >> 2;
    const int m0 = blockIdx.y * P1_BM;
    const int n0 = blockIdx.x * P1_BN;

    float acc[2][8][4];
    #pragma unroll
    for (int i = 0; i < 2; ++i)
        #pragma unroll
        for (int j = 0; j < 8; ++j)
            #pragma unroll
            for (int k = 0; k < 4; ++k) acc[i][j][k] = 0.0f;

    const int lrow = tid >> 1;
    const int lcb  = (tid & 1) * 16;

    const __half* srcA = g_xh     + (size_t)(m0 + lrow) * DIN + lcb;
    const __half* srcB = g_wxhi_h + (size_t)(n0 + lrow) * DIN + lcb;

    auto stage = [&](int s, int k0) {
        __half* a = As + s * P1_PLANE + lrow * P1_ROW + lcb;
        __half* b = Bs + s * P1_PLANE + lrow * P1_ROW + lcb;
        cp16(a,     srcA + k0);
        cp16(a + 8, srcA + k0 + 8);
        cp16(b,     srcB + k0);
        cp16(b + 8, srcB + k0 + 8);
        cp_commit();
    };

    stage(0, 0);
    stage(1, P1_BK);
    stage(2, 2 * P1_BK);

    const int aRow = lane & 15;
    const int aCol = (lane >> 4) << 3;
    const int bRow = ((lane >> 4) << 3) + (lane & 7);
    const int bCol = ((lane >> 3) & 1) << 3;

    const int NIT = DIN / P1_BK;   // 32
    for (int it = 0; it < NIT; ++it) {
        const int buf = it & 3;
        if (it < NIT - 2) cp_wait2();
        else if (it == NIT - 2) cp_wait1();
        else cp_wait0();
        __syncthreads();
        if (it + 3 < NIT) stage((it + 3) & 3, (it + 3) * P1_BK);

        const __half* A = As + buf * P1_PLANE;
        const __half* B = Bs + buf * P1_PLANE;

        #pragma unroll
        for (int kk = 0; kk < 2; ++kk) {
            const int kb = kk * 16;
            unsigned a[2][4];
            #pragma unroll
            for (int mt = 0; mt < 2; ++mt) {
                const int r0 = wm * 32 + mt * 16;
                ldsm_x4(a[mt], A + (r0 + aRow) * P1_ROW + kb + aCol);
            }
            #pragma unroll
            for (int p = 0; p < 4; ++p) {
                const int nb0 = wn * 64 + p * 16;
                unsigned bh[4];
                ldsm_x4(bh, B + (nb0 + bRow) * P1_ROW + kb + bCol);
                #pragma unroll
                for (int mt = 0; mt < 2; ++mt) {
                    #pragma unroll
                    for (int q = 0; q < 2; ++q) {
                        mma16816h(acc[mt][p * 2 + q], a[mt], bh + 2 * q);
                    }
                }
            }
        }
    }

    // epilogue: +bias, store fp32
    const int g = lane >> 2, tg = lane & 3;
    #pragma unroll
    for (int nt = 0; nt < 8; ++nt) {
        const int c = n0 + wn * 64 + nt * 8 + 2 * tg;
        const float bv0 = bias[c], bv1 = bias[c + 1];
        #pragma unroll
        for (int mt = 0; mt < 2; ++mt) {
            const int r0 = m0 + wm * 32 + mt * 16 + g;
            float2 v0 = make_float2(acc[mt][nt][0] + bv0, acc[mt][nt][1] + bv1);
            float2 v1 = make_float2(acc[mt][nt][2] + bv0, acc[mt][nt][3] + bv1);
            *(float2*)&g_xproj[(size_t)r0 * Gsz + c]       = v0;
            *(float2*)&g_xproj[(size_t)(r0 + 8) * Gsz + c] = v1;
        }
    }
}

// ---------------- phase 2: persistent recurrent LSTM (R12 verbatim + release-publish) ----------------
#define NBLK2 128
#define HPERB 8
#define NG 32
#define WPAD 8           // wh row length 1032
#define KC 256
#define HTPAD 8          // htile row length 264
#define NCHUNK (Hsz / KC)   // 4
#define NTH2 512

#define SM_WH   (NG * (Hsz + WPAD))
#define SM_HT   (Bsz * (KC + HTPAD))
#define SMEM_P2 ((size_t)(SM_WH + 2*SM_HT) * 2 + (size_t)(2*Bsz*NG) * 4)

__global__ __launch_bounds__(NTH2, 1) void lstm_kernel(float* __restrict__ out) {
    extern __shared__ char smem[];
    __half* whhi = (__half*)smem;                 // [NG][1032]
    __half* ht[2];
    ht[0] = whhi + SM_WH;                          // [64][264]
    ht[1] = ht[0] + SM_HT;
    float* gates0 = (float*)(ht[1] + SM_HT);       // [64][32] partial K-low
    float* gates1 = gates0 + Bsz * NG;             // [64][32] partial K-high

    const int tid = threadIdx.x;
    const int wid = tid >> 5, lane = tid & 31;
    const int g = lane >> 2, tg = lane & 3;
    const int kgrp = wid >> 3;          // 0: k in [0,128), 1: k in [128,256) of chunk
    const int wl = wid & 7;
    const int wm = wl & 3;              // rows wm*16
    const int wn = wl >> 2;             // cols wn*16
    const int j0 = blockIdx.x * HPERB;
    const int region = blockIdx.x >> 4;

    const int aRow = lane & 15;
    const int aCol = (lane >> 4) << 3;
    const int bRow = wn * 16 + ((lane >> 4) << 3) + (lane & 7);
    const int bCol = ((lane >> 3) & 1) << 3;

    // Wh slice into SMEM (512-scaled fp16, 1-term)
    for (int i = tid; i < NG * (Hsz / 8); i += NTH2) {
        const int n = i >> 7;
        const int cu = i & 127;
        const int q = n >> 3, jj = n & 7;
        const size_t src = (size_t)(q * 1024 + j0 + jj) * Hsz + cu * 8;
        *(uint4*)&whhi[n * (Hsz + WPAD) + cu * 8] = *(const uint4*)(g_whhi_h + src);
    }
    __syncthreads();

    // cell item: one per thread
    const int b_0 = tid >> 3, jj_0 = tid & 7;
    float c_reg = 0.0f;

    // prefetch xproj for step 0
    float xp[4];
    {
        const size_t base0 = ((size_t)b_0 * Lsz) * Gsz + j0 + jj_0;
        xp[0] = __ldg(g_xproj + base0);
        xp[1] = __ldg(g_xproj + base0 + 1024);
        xp[2] = __ldg(g_xproj + base0 + 2048);
        xp[3] = __ldg(g_xproj + base0 + 3072);
    }

    auto stage_h = [&](int buf, int kc, int hbuf) {
        const __half* sh = &g_hh3[hbuf][0];
        #pragma unroll
        for (int q = 0; q < 4; ++q) {
            const int i = tid + q * NTH2;           // 0..2047
            const int row = i >> 5;                 // 32 16B-chunks per row
            const int cu = i & 31;
            cp16(&ht[buf][row * (KC + HTPAD) + cu * 8],
                 sh + (size_t)row * Hsz + kc * KC + cu * 8);
        }
        cp_commit();
    };

    for (int t = 0; t < Lsz; ++t) {
        const int hbuf = t % 3;
        const unsigned need = (unsigned)t * 16;

        // ONE combined wait for all 8 regions (2 volatile v4 loads + acquire fence)
        {
            unsigned m;
            do {
                unsigned r0, r1, r2, r3, r4, r5, r6, r7;
                asm volatile("ld.volatile.global.v4.u32 {%0,%1,%2,%3}, [%4];"
                             : "=r"(r0), "=r"(r1), "=r"(r2), "=r"(r3) : "l"(g_rc));
                asm volatile("ld.volatile.global.v4.u32 {%0,%1,%2,%3}, [%4];"
                             : "=r"(r4), "=r"(r5), "=r"(r6), "=r"(r7) : "l"(g_rc + 4));
                m = umin(umin(umin(r0, r1), umin(r2, r3)),
                         umin(umin(r4, r5), umin(r6, r7)));
            } while (m < need);
            __threadfence();   // acquire for peer h writes
        }

        float acc[2][4];
        #pragma unroll
        for (int i = 0; i < 2; ++i)
            #pragma unroll
            for (int k = 0; k < 4; ++k) acc[i][k] = 0.0f;

        stage_h(0, 0, hbuf);

        for (int kc = 0; kc < NCHUNK; ++kc) {
            const int buf = kc & 1;
            cp_wait0();
            __syncthreads();
            if (kc + 1 < NCHUNK) stage_h(buf ^ 1, kc + 1, hbuf);

            const __half* th = ht[buf];

            // split-K: this warp covers k in [kgrp*128, kgrp*128+128) of the chunk
            #pragma unroll
            for (int ks = 0; ks < 8; ++ks) {
                const int kb = kgrp * 128 + ks * 16;
                unsigned ah[4], bh[4];
                ldsm_x4(ah, th + (wm * 16 + aRow) * (KC + HTPAD) + kb + aCol);
                const int koff = kc * KC + kb + bCol;
                ldsm_x4(bh, whhi + bRow * (Hsz + WPAD) + koff);
                mma16816h(acc[0], ah, bh);
                mma16816h(acc[1], ah, bh + 2);
            }
        }
        __syncthreads();

        // partial gate pre-activations -> SMEM (un-scale 512 here)
        const float IS = 1.0f / 512.0f;
        float* gp = kgrp ? gates1 : gates0;
        #pragma unroll
        for (int nt = 0; nt < 2; ++nt) {
            const int c = wn * 16 + nt * 8 + 2 * tg;
            const int r = wm * 16 + g;
            gp[r * NG + c]           = acc[nt][0] * IS;
            gp[r * NG + c + 1]       = acc[nt][1] * IS;
            gp[(r + 8) * NG + c]     = acc[nt][2] * IS;
            gp[(r + 8) * NG + c + 1] = acc[nt][3] * IS;
        }
        __syncthreads();

        // LSTM cell: 512 items, one per thread; reduce the two K-partials
        const int nb = (t + 1) % 3;
        {
            const int base = b_0 * NG + jj_0;
            const float pf = gates0[base]      + gates1[base]      + xp[0];
            const float pi = gates0[base + 8]  + gates1[base + 8]  + xp[1];
            const float pg = gates0[base + 16] + gates1[base + 16] + xp[2];
            const float po = gates0[base + 24] + gates1[base + 24] + xp[3];
            const float f = sigmoidf_(pf);
            const float ii = sigmoidf_(pi);
            const float gg = tanhf_(pg);
            const float o = sigmoidf_(po);
            c_reg = f * c_reg + ii * gg;
            const float h = o * tanhf_(c_reg);
            out[((size_t)b_0 * Lsz + t) * Hsz + j0 + jj_0] = h;
            g_hh3[nb][b_0 * Hsz + j0 + jj_0] = __float2half(h);
        }

        // publish: bar.sync establishes intra-block HB; release-reduction makes it
        // device-visible (replaces full __threadfence + atomicAdd)
        __syncthreads();
        if (tid == 0) red_release(&g_rc[region], 1u);

        // prefetch xproj for next step
        if (t + 1 < Lsz) {
            const size_t base0 = ((size_t)b_0 * Lsz + (t + 1)) * Gsz + j0 + jj_0;
            xp[0] = __ldg(g_xproj + base0);
            xp[1] = __ldg(g_xproj + base0 + 1024);
            xp[2] = __ldg(g_xproj + base0 + 2048);
            xp[3] = __ldg(g_xproj + base0 + 3072);
        }
    }

    // finals
    {
        const float hv0 = out[((size_t)b_0 * Lsz + (Lsz - 1)) * Hsz + j0 + jj_0];
        out[OUTN + (size_t)b_0 * Hsz + j0 + jj_0] = hv0;
        out[OUTN + (size_t)Bsz * Hsz + (size_t)b_0 * Hsz + j0 + jj_0] = c_reg;
    }
}

// ---------------- launcher ----------------
extern "C" void kernel_launch(void* const* d_in, const int* in_sizes, int n_in,
                              void* d_out, int out_size) {
    const float* x = (const float*)d_in[0];
    const float* W = (const float*)d_in[1];
    const float* b = (const float*)d_in[2];
    float* out = (float*)d_out;

    split_x_kernel<<<2048, 256>>>(x);
    split_w_kernel<<<1024, 256>>>(W);
    init_kernel<<<256, 256>>>();

    cudaFuncSetAttribute(xproj_kernel, cudaFuncAttributeMaxDynamicSharedMemorySize,
                         (int)P1_SMEM);
    dim3 g1(Gsz / P1_BN, ML / P1_BM);   // (32, 256)
    xproj_kernel<<<g1, 256, P1_SMEM>>>(b);

    cudaFuncSetAttribute(lstm_kernel, cudaFuncAttributeMaxDynamicSharedMemorySize,
                         (int)SMEM_P2);
    lstm_kernel<<<NBLK2, NTH2, SMEM_P2>>>(out);
}

// round 15
// speedup vs baseline: 1.3638x; 1.3638x over previous
#include <cuda_runtime.h>
#include <cuda_bf16.h>
#include <cuda_fp16.h>
#include <math.h>
#include <stdint.h>

#define Bsz 64
#define Lsz 512
#define DIN 1024
#define Hsz 1024
#define Gsz 4096
#define ML (Bsz*Lsz)            // 32768
#define OUTN ((size_t)Bsz*Lsz*Hsz) // 33554432

// ---------------- scratch (static device allocations) ----------------
__device__ float g_xproj[(size_t)ML*Gsz];                 // 512 MB
__device__ __half g_xh[(size_t)ML*DIN];        // x in fp16
__device__ __half g_wxhi_h[(size_t)Gsz*DIN];   // Wx fp16 (1-term)
__device__ __half g_whhi_h[(size_t)Gsz*Hsz];   // fp16(512*Wh) (1-term)
__device__ __half g_hh3[3][Bsz*Hsz];           // h, fp16, triple-buffered
__device__ unsigned g_rc[8];    // per-K-region step counters

// ---------------- helpers ----------------
__device__ __forceinline__ void mma16816h(float* c, const unsigned* a, const unsigned* b) {
    asm volatile(
        "mma.sync.aligned.m16n8k16.row.col.f32.f16.f16.f32 "
        "{%0,%1,%2,%3}, {%4,%5,%6,%7}, {%8,%9}, {%0,%1,%2,%3};\n"
        : "+f"(c[0]), "+f"(c[1]), "+f"(c[2]), "+f"(c[3])
        : "r"(a[0]), "r"(a[1]), "r"(a[2]), "r"(a[3]), "r"(b[0]), "r"(b[1]));
}

__device__ __forceinline__ void ldsm_x4(unsigned* r, const void* p) {
    unsigned a = (unsigned)__cvta_generic_to_shared(p);
    asm volatile("ldmatrix.sync.aligned.m8n8.x4.shared.b16 {%0,%1,%2,%3}, [%4];\n"
        : "=r"(r[0]), "=r"(r[1]), "=r"(r[2]), "=r"(r[3]) : "r"(a));
}

__device__ __forceinline__ void cp16(void* dst, const void* src) {
    unsigned d = (unsigned)__cvta_generic_to_shared(dst);
    asm volatile("cp.async.cg.shared.global [%0], [%1], 16;\n" :: "r"(d), "l"(src));
}
__device__ __forceinline__ void cp_commit() { asm volatile("cp.async.commit_group;\n"); }
__device__ __forceinline__ void cp_wait2()  { asm volatile("cp.async.wait_group 2;\n"); }
__device__ __forceinline__ void cp_wait1()  { asm volatile("cp.async.wait_group 1;\n"); }
__device__ __forceinline__ void cp_wait0()  { asm volatile("cp.async.wait_group 0;\n"); }

__device__ __forceinline__ float sigmoidf_(float x) {
    return __fdividef(1.0f, 1.0f + __expf(-x));
}
__device__ __forceinline__ float tanhf_(float x) {
    return __fdividef(2.0f, 1.0f + __expf(-2.0f * x)) - 1.0f;
}

// ---------------- split kernels ----------------
__global__ void split_x_kernel(const float* __restrict__ x) {
    size_t stride = (size_t)gridDim.x * blockDim.x;
    for (size_t i = (size_t)blockIdx.x * blockDim.x + threadIdx.x;
         i < (size_t)ML * DIN; i += stride) {
        g_xh[i] = __float2half(x[i]);
    }
}

__global__ void split_w_kernel(const float* __restrict__ W) {
    size_t stride = (size_t)gridDim.x * blockDim.x;
    for (size_t i = (size_t)blockIdx.x * blockDim.x + threadIdx.x;
         i < (size_t)Gsz * (Hsz + DIN); i += stride) {
        int r = (int)(i >> 11);
        int c = (int)(i & 2047);
        float v = W[i];
        size_t d = (size_t)r * 1024 + (c & 1023);
        if (c < 1024) {
            g_whhi_h[d] = __float2half(v * 512.0f);
        } else {
            g_wxhi_h[d] = __float2half(v);
        }
    }
}

__global__ void init_kernel() {
    int i = blockIdx.x * blockDim.x + threadIdx.x;
    if (i < 8) g_rc[i] = 0;
    if (i < Bsz * Hsz) g_hh3[0][i] = __float2half(0.0f);
}

// ---------------- phase 1: x_proj GEMM (R13 verbatim: 4-stage ring, 1 sync/iter) ----------------
#define P1_BM 128
#define P1_BN 128
#define P1_BK 32
#define P1_ROW 40           // 32 + 8 pad
#define P1_PLANE (P1_BM * P1_ROW)          // elems per stage per matrix (5120)
#define P1_SMEM ((size_t)8 * P1_PLANE * 2) // 4 stages * (A+B) * fp16 = 81920 B

__global__ __launch_bounds__(256, 2) void xproj_kernel(const float* __restrict__ bias) {
    extern __shared__ __half xsm[];
    __half* As = xsm;                      // [4][128][40]
    __half* Bs = xsm + 4 * P1_PLANE;       // [4][128][40]

    const int tid = threadIdx.x;
    const int wid = tid >> 5, lane = tid & 31;
    const int wm = wid & 3;
    const int wn = wid >> 2;
    const int m0 = blockIdx.y * P1_BM;
    const int n0 = blockIdx.x * P1_BN;

    float acc[2][8][4];
    #pragma unroll
    for (int i = 0; i < 2; ++i)
        #pragma unroll
        for (int j = 0; j < 8; ++j)
            #pragma unroll
            for (int k = 0; k < 4; ++k) acc[i][j][k] = 0.0f;

    const int lrow = tid >> 1;
    const int lcb  = (tid & 1) * 16;

    const __half* srcA = g_xh     + (size_t)(m0 + lrow) * DIN + lcb;
    const __half* srcB = g_wxhi_h + (size_t)(n0 + lrow) * DIN + lcb;

    auto stage = [&](int s, int k0) {
        __half* a = As + s * P1_PLANE + lrow * P1_ROW + lcb;
        __half* b = Bs + s * P1_PLANE + lrow * P1_ROW + lcb;
        cp16(a,     srcA + k0);
        cp16(a + 8, srcA + k0 + 8);
        cp16(b,     srcB + k0);
        cp16(b + 8, srcB + k0 + 8);
        cp_commit();
    };

    stage(0, 0);
    stage(1, P1_BK);
    stage(2, 2 * P1_BK);

    const int aRow = lane & 15;
    const int aCol = (lane >> 4) << 3;
    const int bRow = ((lane >> 4) << 3) + (lane & 7);
    const int bCol = ((lane >> 3) & 1) << 3;

    const int NIT = DIN / P1_BK;   // 32
    for (int it = 0; it < NIT; ++it) {
        const int buf = it & 3;
        if (it < NIT - 2) cp_wait2();
        else if (it == NIT - 2) cp_wait1();
        else cp_wait0();
        __syncthreads();
        if (it + 3 < NIT) stage((it + 3) & 3, (it + 3) * P1_BK);

        const __half* A = As + buf * P1_PLANE;
        const __half* B = Bs + buf * P1_PLANE;

        #pragma unroll
        for (int kk = 0; kk < 2; ++kk) {
            const int kb = kk * 16;
            unsigned a[2][4];
            #pragma unroll
            for (int mt = 0; mt < 2; ++mt) {
                const int r0 = wm * 32 + mt * 16;
                ldsm_x4(a[mt], A + (r0 + aRow) * P1_ROW + kb + aCol);
            }
            #pragma unroll
            for (int p = 0; p < 4; ++p) {
                const int nb0 = wn * 64 + p * 16;
                unsigned bh[4];
                ldsm_x4(bh, B + (nb0 + bRow) * P1_ROW + kb + bCol);
                #pragma unroll
                for (int mt = 0; mt < 2; ++mt) {
                    #pragma unroll
                    for (int q = 0; q < 2; ++q) {
                        mma16816h(acc[mt][p * 2 + q], a[mt], bh + 2 * q);
                    }
                }
            }
        }
    }

    // epilogue: +bias, store fp32
    const int g = lane >> 2, tg = lane & 3;
    #pragma unroll
    for (int nt = 0; nt < 8; ++nt) {
        const int c = n0 + wn * 64 + nt * 8 + 2 * tg;
        const float bv0 = bias[c], bv1 = bias[c + 1];
        #pragma unroll
        for (int mt = 0; mt < 2; ++mt) {
            const int r0 = m0 + wm * 32 + mt * 16 + g;
            float2 v0 = make_float2(acc[mt][nt][0] + bv0, acc[mt][nt][1] + bv1);
            float2 v1 = make_float2(acc[mt][nt][2] + bv0, acc[mt][nt][3] + bv1);
            *(float2*)&g_xproj[(size_t)r0 * Gsz + c]       = v0;
            *(float2*)&g_xproj[(size_t)(r0 + 8) * Gsz + c] = v1;
        }
    }
}

// ---------------- phase 2: persistent recurrent LSTM (R12 VERBATIM) ----------------
#define NBLK2 128
#define HPERB 8
#define NG 32
#define WPAD 8           // wh row length 1032
#define KC 256
#define HTPAD 8          // htile row length 264
#define NCHUNK (Hsz / KC)   // 4
#define NTH2 512

#define SM_WH   (NG * (Hsz + WPAD))
#define SM_HT   (Bsz * (KC + HTPAD))
#define SMEM_P2 ((size_t)(SM_WH + 2*SM_HT) * 2 + (size_t)(2*Bsz*NG) * 4)

__global__ __launch_bounds__(NTH2, 1) void lstm_kernel(float* __restrict__ out) {
    extern __shared__ char smem[];
    __half* whhi = (__half*)smem;                 // [NG][1032]
    __half* ht[2];
    ht[0] = whhi + SM_WH;                          // [64][264]
    ht[1] = ht[0] + SM_HT;
    float* gates0 = (float*)(ht[1] + SM_HT);       // [64][32] partial K-low
    float* gates1 = gates0 + Bsz * NG;             // [64][32] partial K-high

    const int tid = threadIdx.x;
    const int wid = tid >> 5, lane = tid & 31;
    const int g = lane >> 2, tg = lane & 3;
    const int kgrp = wid >> 3;          // 0: k in [0,128), 1: k in [128,256) of chunk
    const int wl = wid & 7;
    const int wm = wl & 3;              // rows wm*16
    const int wn = wl >> 2;             // cols wn*16
    const int j0 = blockIdx.x * HPERB;
    const int region = blockIdx.x >> 4;

    const int aRow = lane & 15;
    const int aCol = (lane >> 4) << 3;
    const int bRow = wn * 16 + ((lane >> 4) << 3) + (lane & 7);
    const int bCol = ((lane >> 3) & 1) << 3;

    // Wh slice into SMEM (512-scaled fp16, 1-term)
    for (int i = tid; i < NG * (Hsz / 8); i += NTH2) {
        const int n = i >> 7;
        const int cu = i & 127;
        const int q = n >> 3, jj = n & 7;
        const size_t src = (size_t)(q * 1024 + j0 + jj) * Hsz + cu * 8;
        *(uint4*)&whhi[n * (Hsz + WPAD) + cu * 8] = *(const uint4*)(g_whhi_h + src);
    }
    __syncthreads();

    // cell item: one per thread
    const int b_0 = tid >> 3, jj_0 = tid & 7;
    float c_reg = 0.0f;

    // prefetch xproj for step 0
    float xp[4];
    {
        const size_t base0 = ((size_t)b_0 * Lsz) * Gsz + j0 + jj_0;
        xp[0] = __ldg(g_xproj + base0);
        xp[1] = __ldg(g_xproj + base0 + 1024);
        xp[2] = __ldg(g_xproj + base0 + 2048);
        xp[3] = __ldg(g_xproj + base0 + 3072);
    }

    auto stage_h = [&](int buf, int kc, int hbuf) {
        const __half* sh = &g_hh3[hbuf][0];
        #pragma unroll
        for (int q = 0; q < 4; ++q) {
            const int i = tid + q * NTH2;           // 0..2047
            const int row = i >> 5;                 // 32 16B-chunks per row
            const int cu = i & 31;
            cp16(&ht[buf][row * (KC + HTPAD) + cu * 8],
                 sh + (size_t)row * Hsz + kc * KC + cu * 8);
        }
        cp_commit();
    };

    for (int t = 0; t < Lsz; ++t) {
        const int hbuf = t % 3;
        const unsigned need = (unsigned)t * 16;

        // ONE combined wait for all 8 regions (2 volatile v4 loads + acquire fence)
        {
            unsigned m;
            do {
                unsigned r0, r1, r2, r3, r4, r5, r6, r7;
                asm volatile("ld.volatile.global.v4.u32 {%0,%1,%2,%3}, [%4];"
                             : "=r"(r0), "=r"(r1), "=r"(r2), "=r"(r3) : "l"(g_rc));
                asm volatile("ld.volatile.global.v4.u32 {%0,%1,%2,%3}, [%4];"
                             : "=r"(r4), "=r"(r5), "=r"(r6), "=r"(r7) : "l"(g_rc + 4));
                m = umin(umin(umin(r0, r1), umin(r2, r3)),
                         umin(umin(r4, r5), umin(r6, r7)));
            } while (m < need);
            __threadfence();   // acquire for peer h writes
        }

        float acc[2][4];
        #pragma unroll
        for (int i = 0; i < 2; ++i)
            #pragma unroll
            for (int k = 0; k < 4; ++k) acc[i][k] = 0.0f;

        stage_h(0, 0, hbuf);

        for (int kc = 0; kc < NCHUNK; ++kc) {
            const int buf = kc & 1;
            cp_wait0();
            __syncthreads();
            if (kc + 1 < NCHUNK) stage_h(buf ^ 1, kc + 1, hbuf);

            const __half* th = ht[buf];

            // split-K: this warp covers k in [kgrp*128, kgrp*128+128) of the chunk
            #pragma unroll
            for (int ks = 0; ks < 8; ++ks) {
                const int kb = kgrp * 128 + ks * 16;
                unsigned ah[4], bh[4];
                ldsm_x4(ah, th + (wm * 16 + aRow) * (KC + HTPAD) + kb + aCol);
                const int koff = kc * KC + kb + bCol;
                ldsm_x4(bh, whhi + bRow * (Hsz + WPAD) + koff);
                mma16816h(acc[0], ah, bh);
                mma16816h(acc[1], ah, bh + 2);
            }
        }
        __syncthreads();

        // partial gate pre-activations -> SMEM (un-scale 512 here)
        const float IS = 1.0f / 512.0f;
        float* gp = kgrp ? gates1 : gates0;
        #pragma unroll
        for (int nt = 0; nt < 2; ++nt) {
            const int c = wn * 16 + nt * 8 + 2 * tg;
            const int r = wm * 16 + g;
            gp[r * NG + c]           = acc[nt][0] * IS;
            gp[r * NG + c + 1]       = acc[nt][1] * IS;
            gp[(r + 8) * NG + c]     = acc[nt][2] * IS;
            gp[(r + 8) * NG + c + 1] = acc[nt][3] * IS;
        }
        __syncthreads();

        // LSTM cell: 512 items, one per thread; reduce the two K-partials
        const int nb = (t + 1) % 3;
        {
            const int base = b_0 * NG + jj_0;
            const float pf = gates0[base]      + gates1[base]      + xp[0];
            const float pi = gates0[base + 8]  + gates1[base + 8]  + xp[1];
            const float pg = gates0[base + 16] + gates1[base + 16] + xp[2];
            const float po = gates0[base + 24] + gates1[base + 24] + xp[3];
            const float f = sigmoidf_(pf);
            const float ii = sigmoidf_(pi);
            const float gg = tanhf_(pg);
            const float o = sigmoidf_(po);
            c_reg = f * c_reg + ii * gg;
            const float h = o * tanhf_(c_reg);
            out[((size_t)b_0 * Lsz + t) * Hsz + j0 + jj_0] = h;
            g_hh3[nb][b_0 * Hsz + j0 + jj_0] = __float2half(h);
        }

        // publish: this block finished step t for its region (R12 pattern)
        __threadfence();
        __syncthreads();
        if (tid == 0) atomicAdd(&g_rc[region], 1u);

        // prefetch xproj for next step
        if (t + 1 < Lsz) {
            const size_t base0 = ((size_t)b_0 * Lsz + (t + 1)) * Gsz + j0 + jj_0;
            xp[0] = __ldg(g_xproj + base0);
            xp[1] = __ldg(g_xproj + base0 + 1024);
            xp[2] = __ldg(g_xproj + base0 + 2048);
            xp[3] = __ldg(g_xproj + base0 + 3072);
        }
    }

    // finals
    {
        const float hv0 = out[((size_t)b_0 * Lsz + (Lsz - 1)) * Hsz + j0 + jj_0];
        out[OUTN + (size_t)b_0 * Hsz + j0 + jj_0] = hv0;
        out[OUTN + (size_t)Bsz * Hsz + (size_t)b_0 * Hsz + j0 + jj_0] = c_reg;
    }
}

// ---------------- launcher ----------------
extern "C" void kernel_launch(void* const* d_in, const int* in_sizes, int n_in,
                              void* d_out, int out_size) {
    const float* x = (const float*)d_in[0];
    const float* W = (const float*)d_in[1];
    const float* b = (const float*)d_in[2];
    float* out = (float*)d_out;

    split_x_kernel<<<2048, 256>>>(x);
    split_w_kernel<<<1024, 256>>>(W);
    init_kernel<<<256, 256>>>();

    cudaFuncSetAttribute(xproj_kernel, cudaFuncAttributeMaxDynamicSharedMemorySize,
                         (int)P1_SMEM);
    dim3 g1(Gsz / P1_BN, ML / P1_BM);   // (32, 256)
    xproj_kernel<<<g1, 256, P1_SMEM>>>(b);

    cudaFuncSetAttribute(lstm_kernel, cudaFuncAttributeMaxDynamicSharedMemorySize,
                         (int)SMEM_P2);
    lstm_kernel<<<NBLK2, NTH2, SMEM_P2>>>(out);
}

// round 16
// speedup vs baseline: 1.3875x; 1.0174x over previous
#include <cuda_runtime.h>
#include <cuda_bf16.h>
#include <cuda_fp16.h>
#include <math.h>
#include <stdint.h>

#define Bsz 64
#define Lsz 512
#define DIN 1024
#define Hsz 1024
#define Gsz 4096
#define ML (Bsz*Lsz)            // 32768
#define OUTN ((size_t)Bsz*Lsz*Hsz) // 33554432

// ---------------- scratch (static device allocations) ----------------
__device__ float g_xproj[(size_t)ML*Gsz];                 // 512 MB
__device__ __half g_xh[(size_t)ML*DIN];        // x in fp16
__device__ __half g_wxhi_h[(size_t)Gsz*DIN];   // Wx fp16 (1-term)
__device__ __half g_whhi_h[(size_t)Gsz*Hsz];   // fp16(512*Wh) (1-term)
__device__ __half g_hh3[3][Bsz*Hsz];           // h, fp16, triple-buffered
__device__ unsigned g_rc[8];    // per-K-region step counters

// ---------------- helpers ----------------
__device__ __forceinline__ void mma16816h(float* c, const unsigned* a, const unsigned* b) {
    asm volatile(
        "mma.sync.aligned.m16n8k16.row.col.f32.f16.f16.f32 "
        "{%0,%1,%2,%3}, {%4,%5,%6,%7}, {%8,%9}, {%0,%1,%2,%3};\n"
        : "+f"(c[0]), "+f"(c[1]), "+f"(c[2]), "+f"(c[3])
        : "r"(a[0]), "r"(a[1]), "r"(a[2]), "r"(a[3]), "r"(b[0]), "r"(b[1]));
}

__device__ __forceinline__ void ldsm_x4(unsigned* r, const void* p) {
    unsigned a = (unsigned)__cvta_generic_to_shared(p);
    asm volatile("ldmatrix.sync.aligned.m8n8.x4.shared.b16 {%0,%1,%2,%3}, [%4];\n"
        : "=r"(r[0]), "=r"(r[1]), "=r"(r[2]), "=r"(r[3]) : "r"(a));
}

__device__ __forceinline__ void cp16(void* dst, const void* src) {
    unsigned d = (unsigned)__cvta_generic_to_shared(dst);
    asm volatile("cp.async.cg.shared.global [%0], [%1], 16;\n" :: "r"(d), "l"(src));
}
__device__ __forceinline__ void cp_commit() { asm volatile("cp.async.commit_group;\n"); }
__device__ __forceinline__ void cp_wait1()  { asm volatile("cp.async.wait_group 1;\n"); }
__device__ __forceinline__ void cp_wait0()  { asm volatile("cp.async.wait_group 0;\n"); }

__device__ __forceinline__ float sigmoidf_(float x) {
    return __fdividef(1.0f, 1.0f + __expf(-x));
}
__device__ __forceinline__ float tanhf_(float x) {
    return __fdividef(2.0f, 1.0f + __expf(-2.0f * x)) - 1.0f;
}

// ---------------- split kernels ----------------
__global__ void split_x_kernel(const float* __restrict__ x) {
    size_t stride = (size_t)gridDim.x * blockDim.x;
    for (size_t i = (size_t)blockIdx.x * blockDim.x + threadIdx.x;
         i < (size_t)ML * DIN; i += stride) {
        g_xh[i] = __float2half(x[i]);
    }
}

__global__ void split_w_kernel(const float* __restrict__ W) {
    size_t stride = (size_t)gridDim.x * blockDim.x;
    for (size_t i = (size_t)blockIdx.x * blockDim.x + threadIdx.x;
         i < (size_t)Gsz * (Hsz + DIN); i += stride) {
        int r = (int)(i >> 11);
        int c = (int)(i & 2047);
        float v = W[i];
        size_t d = (size_t)r * 1024 + (c & 1023);
        if (c < 1024) {
            g_whhi_h[d] = __float2half(v * 512.0f);
        } else {
            g_wxhi_h[d] = __float2half(v);
        }
    }
}

__global__ void init_kernel() {
    int i = blockIdx.x * blockDim.x + threadIdx.x;
    if (i < 8) g_rc[i] = 0;
    if (i < Bsz * Hsz) g_hh3[0][i] = __float2half(0.0f);
}

// ---------------- phase 1: x_proj GEMM (BK=64, 3-stage ring, 1 sync/iter) ----------------
#define P1_BM 128
#define P1_BN 128
#define P1_BK 64
#define P1_ROW 72           // 64 + 8 pad
#define P1_PLANE (P1_BM * P1_ROW)          // 9216 halfs per stage per matrix
#define P1_SMEM ((size_t)6 * P1_PLANE * 2) // 3 stages * (A+B) * fp16 = 110592 B

__global__ __launch_bounds__(256, 2) void xproj_kernel(const float* __restrict__ bias) {
    extern __shared__ __half xsm[];
    __half* As = xsm;                      // [3][128][72]
    __half* Bs = xsm + 3 * P1_PLANE;       // [3][128][72]

    const int tid = threadIdx.x;
    const int wid = tid >> 5, lane = tid & 31;
    const int wm = wid & 3;
    const int wn = wid >> 2;
    const int m0 = blockIdx.y * P1_BM;
    const int n0 = blockIdx.x * P1_BN;

    float acc[2][8][4];
    #pragma unroll
    for (int i = 0; i < 2; ++i)
        #pragma unroll
        for (int j = 0; j < 8; ++j)
            #pragma unroll
            for (int k = 0; k < 4; ++k) acc[i][j][k] = 0.0f;

    const int lrow = tid >> 1;            // 0..127
    const int lcb  = (tid & 1) * 32;      // 0 or 32 (halfs)

    const __half* srcA = g_xh     + (size_t)(m0 + lrow) * DIN + lcb;
    const __half* srcB = g_wxhi_h + (size_t)(n0 + lrow) * DIN + lcb;

    auto stage = [&](int s, int k0) {
        __half* a = As + s * P1_PLANE + lrow * P1_ROW + lcb;
        __half* b = Bs + s * P1_PLANE + lrow * P1_ROW + lcb;
        #pragma unroll
        for (int c = 0; c < 4; ++c) {
            cp16(a + c * 8, srcA + k0 + c * 8);
            cp16(b + c * 8, srcB + k0 + c * 8);
        }
        cp_commit();
    };

    stage(0, 0);
    stage(1, P1_BK);

    const int aRow = lane & 15;
    const int aCol = (lane >> 4) << 3;
    const int bRow = ((lane >> 4) << 3) + (lane & 7);
    const int bCol = ((lane >> 3) & 1) << 3;

    const int NIT = DIN / P1_BK;   // 16
    int buf = 0;
    for (int it = 0; it < NIT; ++it) {
        if (it < NIT - 1) cp_wait1(); else cp_wait0();
        __syncthreads();
        if (it + 2 < NIT) stage((it + 2) % 3, (it + 2) * P1_BK);

        const __half* A = As + buf * P1_PLANE;
        const __half* B = Bs + buf * P1_PLANE;

        #pragma unroll
        for (int kk = 0; kk < 4; ++kk) {
            const int kb = kk * 16;
            unsigned a[2][4];
            #pragma unroll
            for (int mt = 0; mt < 2; ++mt) {
                const int r0 = wm * 32 + mt * 16;
                ldsm_x4(a[mt], A + (r0 + aRow) * P1_ROW + kb + aCol);
            }
            #pragma unroll
            for (int p = 0; p < 4; ++p) {
                const int nb0 = wn * 64 + p * 16;
                unsigned bh[4];
                ldsm_x4(bh, B + (nb0 + bRow) * P1_ROW + kb + bCol);
                #pragma unroll
                for (int mt = 0; mt < 2; ++mt) {
                    #pragma unroll
                    for (int q = 0; q < 2; ++q) {
                        mma16816h(acc[mt][p * 2 + q], a[mt], bh + 2 * q);
                    }
                }
            }
        }
        buf = (buf + 1) % 3;
    }

    // epilogue: +bias, store fp32
    const int g = lane >> 2, tg = lane & 3;
    #pragma unroll
    for (int nt = 0; nt < 8; ++nt) {
        const int c = n0 + wn * 64 + nt * 8 + 2 * tg;
        const float bv0 = bias[c], bv1 = bias[c + 1];
        #pragma unroll
        for (int mt = 0; mt < 2; ++mt) {
            const int r0 = m0 + wm * 32 + mt * 16 + g;
            float2 v0 = make_float2(acc[mt][nt][0] + bv0, acc[mt][nt][1] + bv1);
            float2 v1 = make_float2(acc[mt][nt][2] + bv0, acc[mt][nt][3] + bv1);
            *(float2*)&g_xproj[(size_t)r0 * Gsz + c]       = v0;
            *(float2*)&g_xproj[(size_t)(r0 + 8) * Gsz + c] = v1;
        }
    }
}

// ---------------- phase 2: persistent recurrent LSTM (R12 + warp-0 poll, 1 fewer barrier) ----------------
#define NBLK2 128
#define HPERB 8
#define NG 32
#define WPAD 8           // wh row length 1032
#define KC 256
#define HTPAD 8          // htile row length 264
#define NCHUNK (Hsz / KC)   // 4
#define NTH2 512

#define SM_WH   (NG * (Hsz + WPAD))
#define SM_HT   (Bsz * (KC + HTPAD))
#define SMEM_P2 ((size_t)(SM_WH + 2*SM_HT) * 2 + (size_t)(2*Bsz*NG) * 4)

__global__ __launch_bounds__(NTH2, 1) void lstm_kernel(float* __restrict__ out) {
    extern __shared__ char smem[];
    __half* whhi = (__half*)smem;                 // [NG][1032]
    __half* ht[2];
    ht[0] = whhi + SM_WH;                          // [64][264]
    ht[1] = ht[0] + SM_HT;
    float* gates0 = (float*)(ht[1] + SM_HT);       // [64][32] partial K-low
    float* gates1 = gates0 + Bsz * NG;             // [64][32] partial K-high

    const int tid = threadIdx.x;
    const int wid = tid >> 5, lane = tid & 31;
    const int g = lane >> 2, tg = lane & 3;
    const int kgrp = wid >> 3;          // 0: k in [0,128), 1: k in [128,256) of chunk
    const int wl = wid & 7;
    const int wm = wl & 3;              // rows wm*16
    const int wn = wl >> 2;             // cols wn*16
    const int j0 = blockIdx.x * HPERB;
    const int region = blockIdx.x >> 4;

    const int aRow = lane & 15;
    const int aCol = (lane >> 4) << 3;
    const int bRow = wn * 16 + ((lane >> 4) << 3) + (lane & 7);
    const int bCol = ((lane >> 3) & 1) << 3;

    // Wh slice into SMEM (512-scaled fp16, 1-term)
    for (int i = tid; i < NG * (Hsz / 8); i += NTH2) {
        const int n = i >> 7;
        const int cu = i & 127;
        const int q = n >> 3, jj = n & 7;
        const size_t src = (size_t)(q * 1024 + j0 + jj) * Hsz + cu * 8;
        *(uint4*)&whhi[n * (Hsz + WPAD) + cu * 8] = *(const uint4*)(g_whhi_h + src);
    }
    __syncthreads();

    // cell item: one per thread
    const int b_0 = tid >> 3, jj_0 = tid & 7;
    float c_reg = 0.0f;

    // prefetch xproj for step 0
    float xp[4];
    {
        const size_t base0 = ((size_t)b_0 * Lsz) * Gsz + j0 + jj_0;
        xp[0] = __ldg(g_xproj + base0);
        xp[1] = __ldg(g_xproj + base0 + 1024);
        xp[2] = __ldg(g_xproj + base0 + 2048);
        xp[3] = __ldg(g_xproj + base0 + 3072);
    }

    auto stage_h = [&](int buf, int kc, int hbuf) {
        const __half* sh = &g_hh3[hbuf][0];
        #pragma unroll
        for (int q = 0; q < 4; ++q) {
            const int i = tid + q * NTH2;           // 0..2047
            const int row = i >> 5;                 // 32 16B-chunks per row
            const int cu = i & 31;
            cp16(&ht[buf][row * (KC + HTPAD) + cu * 8],
                 sh + (size_t)row * Hsz + kc * KC + cu * 8);
        }
        cp_commit();
    };

    for (int t = 0; t < Lsz; ++t) {
        const int hbuf = t % 3;
        const unsigned need = (unsigned)t * 16;

        // warp 0 polls all 8 region counters; barrier hands HB to the block
        if (wid == 0) {
            unsigned m;
            do {
                unsigned r0, r1, r2, r3, r4, r5, r6, r7;
                asm volatile("ld.volatile.global.v4.u32 {%0,%1,%2,%3}, [%4];"
                             : "=r"(r0), "=r"(r1), "=r"(r2), "=r"(r3) : "l"(g_rc));
                asm volatile("ld.volatile.global.v4.u32 {%0,%1,%2,%3}, [%4];"
                             : "=r"(r4), "=r"(r5), "=r"(r6), "=r"(r7) : "l"(g_rc + 4));
                m = umin(umin(umin(r0, r1), umin(r2, r3)),
                         umin(umin(r4, r5), umin(r6, r7)));
            } while (m < need);
            __threadfence();   // acquire for peer h writes
        }
        __syncthreads();

        float acc[2][4];
        #pragma unroll
        for (int i = 0; i < 2; ++i)
            #pragma unroll
            for (int k = 0; k < 4; ++k) acc[i][k] = 0.0f;

        stage_h(0, 0, hbuf);

        for (int kc = 0; kc < NCHUNK; ++kc) {
            const int buf = kc & 1;
            cp_wait0();
            __syncthreads();
            if (kc + 1 < NCHUNK) stage_h(buf ^ 1, kc + 1, hbuf);

            const __half* th = ht[buf];

            // split-K: this warp covers k in [kgrp*128, kgrp*128+128) of the chunk
            #pragma unroll
            for (int ks = 0; ks < 8; ++ks) {
                const int kb = kgrp * 128 + ks * 16;
                unsigned ah[4], bh[4];
                ldsm_x4(ah, th + (wm * 16 + aRow) * (KC + HTPAD) + kb + aCol);
                const int koff = kc * KC + kb + bCol;
                ldsm_x4(bh, whhi + bRow * (Hsz + WPAD) + koff);
                mma16816h(acc[0], ah, bh);
                mma16816h(acc[1], ah, bh + 2);
            }
        }

        // partial gate pre-activations -> SMEM (un-scale 512 here).
        // No barrier needed before this write: the publish barrier of step t-1
        // already ordered the previous cell reads of gates0/gates1.
        const float IS = 1.0f / 512.0f;
        float* gp = kgrp ? gates1 : gates0;
        #pragma unroll
        for (int nt = 0; nt < 2; ++nt) {
            const int c = wn * 16 + nt * 8 + 2 * tg;
            const int r = wm * 16 + g;
            gp[r * NG + c]           = acc[nt][0] * IS;
            gp[r * NG + c + 1]       = acc[nt][1] * IS;
            gp[(r + 8) * NG + c]     = acc[nt][2] * IS;
            gp[(r + 8) * NG + c + 1] = acc[nt][3] * IS;
        }
        __syncthreads();

        // LSTM cell: 512 items, one per thread; reduce the two K-partials
        const int nb = (t + 1) % 3;
        {
            const int base = b_0 * NG + jj_0;
            const float pf = gates0[base]      + gates1[base]      + xp[0];
            const float pi = gates0[base + 8]  + gates1[base + 8]  + xp[1];
            const float pg = gates0[base + 16] + gates1[base + 16] + xp[2];
            const float po = gates0[base + 24] + gates1[base + 24] + xp[3];
            const float f = sigmoidf_(pf);
            const float ii = sigmoidf_(pi);
            const float gg = tanhf_(pg);
            const float o = sigmoidf_(po);
            c_reg = f * c_reg + ii * gg;
            const float h = o * tanhf_(c_reg);
            out[((size_t)b_0 * Lsz + t) * Hsz + j0 + jj_0] = h;
            g_hh3[nb][b_0 * Hsz + j0 + jj_0] = __float2half(h);
        }

        // publish: this block finished step t for its region (R12 pattern)
        __threadfence();
        __syncthreads();
        if (tid == 0) atomicAdd(&g_rc[region], 1u);

        // prefetch xproj for next step
        if (t + 1 < Lsz) {
            const size_t base0 = ((size_t)b_0 * Lsz + (t + 1)) * Gsz + j0 + jj_0;
            xp[0] = __ldg(g_xproj + base0);
            xp[1] = __ldg(g_xproj + base0 + 1024);
            xp[2] = __ldg(g_xproj + base0 + 2048);
            xp[3] = __ldg(g_xproj + base0 + 3072);
        }
    }

    // finals
    {
        const float hv0 = out[((size_t)b_0 * Lsz + (Lsz - 1)) * Hsz + j0 + jj_0];
        out[OUTN + (size_t)b_0 * Hsz + j0 + jj_0] = hv0;
        out[OUTN + (size_t)Bsz * Hsz + (size_t)b_0 * Hsz + j0 + jj_0] = c_reg;
    }
}

// ---------------- launcher ----------------
extern "C" void kernel_launch(void* const* d_in, const int* in_sizes, int n_in,
                              void* d_out, int out_size) {
    const float* x = (const float*)d_in[0];
    const float* W = (const float*)d_in[1];
    const float* b = (const float*)d_in[2];
    float* out = (float*)d_out;

    split_x_kernel<<<2048, 256>>>(x);
    split_w_kernel<<<1024, 256>>>(W);
    init_kernel<<<256, 256>>>();

    cudaFuncSetAttribute(xproj_kernel, cudaFuncAttributeMaxDynamicSharedMemorySize,
                         (int)P1_SMEM);
    dim3 g1(Gsz / P1_BN, ML / P1_BM);   // (32, 256)
    xproj_kernel<<<g1, 256, P1_SMEM>>>(b);

    cudaFuncSetAttribute(lstm_kernel, cudaFuncAttributeMaxDynamicSharedMemorySize,
                         (int)SMEM_P2);
    lstm_kernel<<<NBLK2, NTH2, SMEM_P2>>>(out);
}

// round 17
// speedup vs baseline: 1.4130x; 1.0184x over previous
#include <cuda_runtime.h>
#include <cuda_bf16.h>
#include <cuda_fp16.h>
#include <math.h>
#include <stdint.h>

#define Bsz 64
#define Lsz 512
#define DIN 1024
#define Hsz 1024
#define Gsz 4096
#define ML (Bsz*Lsz)            // 32768
#define OUTN ((size_t)Bsz*Lsz*Hsz) // 33554432

// ---------------- scratch (static device allocations) ----------------
__device__ float g_xproj[(size_t)ML*Gsz];                 // 512 MB
__device__ __half g_xh[(size_t)ML*DIN];        // x in fp16
__device__ __half g_wxhi_h[(size_t)Gsz*DIN];   // Wx fp16 (1-term)
__device__ __half g_whhi_h[(size_t)Gsz*Hsz];   // fp16(512*Wh) (1-term)
__device__ __half g_hh3[3][Bsz*Hsz];           // h, fp16, triple-buffered
__device__ unsigned g_rc[8];    // per-K-region step counters

// ---------------- helpers ----------------
__device__ __forceinline__ void mma16816h(float* c, const unsigned* a, const unsigned* b) {
    asm volatile(
        "mma.sync.aligned.m16n8k16.row.col.f32.f16.f16.f32 "
        "{%0,%1,%2,%3}, {%4,%5,%6,%7}, {%8,%9}, {%0,%1,%2,%3};\n"
        : "+f"(c[0]), "+f"(c[1]), "+f"(c[2]), "+f"(c[3])
        : "r"(a[0]), "r"(a[1]), "r"(a[2]), "r"(a[3]), "r"(b[0]), "r"(b[1]));
}

__device__ __forceinline__ void ldsm_x4(unsigned* r, const void* p) {
    unsigned a = (unsigned)__cvta_generic_to_shared(p);
    asm volatile("ldmatrix.sync.aligned.m8n8.x4.shared.b16 {%0,%1,%2,%3}, [%4];\n"
        : "=r"(r[0]), "=r"(r[1]), "=r"(r[2]), "=r"(r[3]) : "r"(a));
}

__device__ __forceinline__ void cp16(void* dst, const void* src) {
    unsigned d = (unsigned)__cvta_generic_to_shared(dst);
    asm volatile("cp.async.cg.shared.global [%0], [%1], 16;\n" :: "r"(d), "l"(src));
}
__device__ __forceinline__ void cp_commit() { asm volatile("cp.async.commit_group;\n"); }
__device__ __forceinline__ void cp_wait2()  { asm volatile("cp.async.wait_group 2;\n"); }
__device__ __forceinline__ void cp_wait1()  { asm volatile("cp.async.wait_group 1;\n"); }
__device__ __forceinline__ void cp_wait0()  { asm volatile("cp.async.wait_group 0;\n"); }

__device__ __forceinline__ float sigmoidf_(float x) {
    return __fdividef(1.0f, 1.0f + __expf(-x));
}
__device__ __forceinline__ float tanhf_(float x) {
    return __fdividef(2.0f, 1.0f + __expf(-2.0f * x)) - 1.0f;
}

// ---------------- split kernels ----------------
__global__ void split_x_kernel(const float* __restrict__ x) {
    size_t stride = (size_t)gridDim.x * blockDim.x;
    for (size_t i = (size_t)blockIdx.x * blockDim.x + threadIdx.x;
         i < (size_t)ML * DIN; i += stride) {
        g_xh[i] = __float2half(x[i]);
    }
}

__global__ void split_w_kernel(const float* __restrict__ W) {
    size_t stride = (size_t)gridDim.x * blockDim.x;
    for (size_t i = (size_t)blockIdx.x * blockDim.x + threadIdx.x;
         i < (size_t)Gsz * (Hsz + DIN); i += stride) {
        int r = (int)(i >> 11);
        int c = (int)(i & 2047);
        float v = W[i];
        size_t d = (size_t)r * 1024 + (c & 1023);
        if (c < 1024) {
            g_whhi_h[d] = __float2half(v * 512.0f);
        } else {
            g_wxhi_h[d] = __float2half(v);
        }
    }
}

__global__ void init_kernel() {
    int i = blockIdx.x * blockDim.x + threadIdx.x;
    if (i < 8) g_rc[i] = 0;
    if (i < Bsz * Hsz) g_hh3[0][i] = __float2half(0.0f);
}

// ---------------- phase 1: x_proj GEMM (R15 verbatim: BK=32, 4-stage ring, 1 sync/iter) ----------------
#define P1_BM 128
#define P1_BN 128
#define P1_BK 32
#define P1_ROW 40           // 32 + 8 pad
#define P1_PLANE (P1_BM * P1_ROW)          // elems per stage per matrix (5120)
#define P1_SMEM ((size_t)8 * P1_PLANE * 2) // 4 stages * (A+B) * fp16 = 81920 B

__global__ __launch_bounds__(256, 2) void xproj_kernel(const float* __restrict__ bias) {
    extern __shared__ __half xsm[];
    __half* As = xsm;                      // [4][128][40]
    __half* Bs = xsm + 4 * P1_PLANE;       // [4][128][40]

    const int tid = threadIdx.x;
    const int wid = tid >> 5, lane = tid & 31;
    const int wm = wid & 3;
    const int wn = wid >> 2;
    const int m0 = blockIdx.y * P1_BM;
    const int n0 = blockIdx.x * P1_BN;

    float acc[2][8][4];
    #pragma unroll
    for (int i = 0; i < 2; ++i)
        #pragma unroll
        for (int j = 0; j < 8; ++j)
            #pragma unroll
            for (int k = 0; k < 4; ++k) acc[i][j][k] = 0.0f;

    const int lrow = tid >> 1;
    const int lcb  = (tid & 1) * 16;

    const __half* srcA = g_xh     + (size_t)(m0 + lrow) * DIN + lcb;
    const __half* srcB = g_wxhi_h + (size_t)(n0 + lrow) * DIN + lcb;

    auto stage = [&](int s, int k0) {
        __half* a = As + s * P1_PLANE + lrow * P1_ROW + lcb;
        __half* b = Bs + s * P1_PLANE + lrow * P1_ROW + lcb;
        cp16(a,     srcA + k0);
        cp16(a + 8, srcA + k0 + 8);
        cp16(b,     srcB + k0);
        cp16(b + 8, srcB + k0 + 8);
        cp_commit();
    };

    stage(0, 0);
    stage(1, P1_BK);
    stage(2, 2 * P1_BK);

    const int aRow = lane & 15;
    const int aCol = (lane >> 4) << 3;
    const int bRow = ((lane >> 4) << 3) + (lane & 7);
    const int bCol = ((lane >> 3) & 1) << 3;

    const int NIT = DIN / P1_BK;   // 32
    for (int it = 0; it < NIT; ++it) {
        const int buf = it & 3;
        if (it < NIT - 2) cp_wait2();
        else if (it == NIT - 2) cp_wait1();
        else cp_wait0();
        __syncthreads();
        if (it + 3 < NIT) stage((it + 3) & 3, (it + 3) * P1_BK);

        const __half* A = As + buf * P1_PLANE;
        const __half* B = Bs + buf * P1_PLANE;

        #pragma unroll
        for (int kk = 0; kk < 2; ++kk) {
            const int kb = kk * 16;
            unsigned a[2][4];
            #pragma unroll
            for (int mt = 0; mt < 2; ++mt) {
                const int r0 = wm * 32 + mt * 16;
                ldsm_x4(a[mt], A + (r0 + aRow) * P1_ROW + kb + aCol);
            }
            #pragma unroll
            for (int p = 0; p < 4; ++p) {
                const int nb0 = wn * 64 + p * 16;
                unsigned bh[4];
                ldsm_x4(bh, B + (nb0 + bRow) * P1_ROW + kb + bCol);
                #pragma unroll
                for (int mt = 0; mt < 2; ++mt) {
                    #pragma unroll
                    for (int q = 0; q < 2; ++q) {
                        mma16816h(acc[mt][p * 2 + q], a[mt], bh + 2 * q);
                    }
                }
            }
        }
    }

    // epilogue: +bias, store fp32
    const int g = lane >> 2, tg = lane & 3;
    #pragma unroll
    for (int nt = 0; nt < 8; ++nt) {
        const int c = n0 + wn * 64 + nt * 8 + 2 * tg;
        const float bv0 = bias[c], bv1 = bias[c + 1];
        #pragma unroll
        for (int mt = 0; mt < 2; ++mt) {
            const int r0 = m0 + wm * 32 + mt * 16 + g;
            float2 v0 = make_float2(acc[mt][nt][0] + bv0, acc[mt][nt][1] + bv1);
            float2 v1 = make_float2(acc[mt][nt][2] + bv0, acc[mt][nt][3] + bv1);
            *(float2*)&g_xproj[(size_t)r0 * Gsz + c]       = v0;
            *(float2*)&g_xproj[(size_t)(r0 + 8) * Gsz + c] = v1;
        }
    }
}

// ---------------- phase 2: persistent recurrent LSTM (R16 VERBATIM) ----------------
#define NBLK2 128
#define HPERB 8
#define NG 32
#define WPAD 8           // wh row length 1032
#define KC 256
#define HTPAD 8          // htile row length 264
#define NCHUNK (Hsz / KC)   // 4
#define NTH2 512

#define SM_WH   (NG * (Hsz + WPAD))
#define SM_HT   (Bsz * (KC + HTPAD))
#define SMEM_P2 ((size_t)(SM_WH + 2*SM_HT) * 2 + (size_t)(2*Bsz*NG) * 4)

__global__ __launch_bounds__(NTH2, 1) void lstm_kernel(float* __restrict__ out) {
    extern __shared__ char smem[];
    __half* whhi = (__half*)smem;                 // [NG][1032]
    __half* ht[2];
    ht[0] = whhi + SM_WH;                          // [64][264]
    ht[1] = ht[0] + SM_HT;
    float* gates0 = (float*)(ht[1] + SM_HT);       // [64][32] partial K-low
    float* gates1 = gates0 + Bsz * NG;             // [64][32] partial K-high

    const int tid = threadIdx.x;
    const int wid = tid >> 5, lane = tid & 31;
    const int g = lane >> 2, tg = lane & 3;
    const int kgrp = wid >> 3;          // 0: k in [0,128), 1: k in [128,256) of chunk
    const int wl = wid & 7;
    const int wm = wl & 3;              // rows wm*16
    const int wn = wl >> 2;             // cols wn*16
    const int j0 = blockIdx.x * HPERB;
    const int region = blockIdx.x >> 4;

    const int aRow = lane & 15;
    const int aCol = (lane >> 4) << 3;
    const int bRow = wn * 16 + ((lane >> 4) << 3) + (lane & 7);
    const int bCol = ((lane >> 3) & 1) << 3;

    // Wh slice into SMEM (512-scaled fp16, 1-term)
    for (int i = tid; i < NG * (Hsz / 8); i += NTH2) {
        const int n = i >> 7;
        const int cu = i & 127;
        const int q = n >> 3, jj = n & 7;
        const size_t src = (size_t)(q * 1024 + j0 + jj) * Hsz + cu * 8;
        *(uint4*)&whhi[n * (Hsz + WPAD) + cu * 8] = *(const uint4*)(g_whhi_h + src);
    }
    __syncthreads();

    // cell item: one per thread
    const int b_0 = tid >> 3, jj_0 = tid & 7;
    float c_reg = 0.0f;

    // prefetch xproj for step 0
    float xp[4];
    {
        const size_t base0 = ((size_t)b_0 * Lsz) * Gsz + j0 + jj_0;
        xp[0] = __ldg(g_xproj + base0);
        xp[1] = __ldg(g_xproj + base0 + 1024);
        xp[2] = __ldg(g_xproj + base0 + 2048);
        xp[3] = __ldg(g_xproj + base0 + 3072);
    }

    auto stage_h = [&](int buf, int kc, int hbuf) {
        const __half* sh = &g_hh3[hbuf][0];
        #pragma unroll
        for (int q = 0; q < 4; ++q) {
            const int i = tid + q * NTH2;           // 0..2047
            const int row = i >> 5;                 // 32 16B-chunks per row
            const int cu = i & 31;
            cp16(&ht[buf][row * (KC + HTPAD) + cu * 8],
                 sh + (size_t)row * Hsz + kc * KC + cu * 8);
        }
        cp_commit();
    };

    for (int t = 0; t < Lsz; ++t) {
        const int hbuf = t % 3;
        const unsigned need = (unsigned)t * 16;

        // warp 0 polls all 8 region counters; barrier hands HB to the block
        if (wid == 0) {
            unsigned m;
            do {
                unsigned r0, r1, r2, r3, r4, r5, r6, r7;
                asm volatile("ld.volatile.global.v4.u32 {%0,%1,%2,%3}, [%4];"
                             : "=r"(r0), "=r"(r1), "=r"(r2), "=r"(r3) : "l"(g_rc));
                asm volatile("ld.volatile.global.v4.u32 {%0,%1,%2,%3}, [%4];"
                             : "=r"(r4), "=r"(r5), "=r"(r6), "=r"(r7) : "l"(g_rc + 4));
                m = umin(umin(umin(r0, r1), umin(r2, r3)),
                         umin(umin(r4, r5), umin(r6, r7)));
            } while (m < need);
            __threadfence();   // acquire for peer h writes
        }
        __syncthreads();

        float acc[2][4];
        #pragma unroll
        for (int i = 0; i < 2; ++i)
            #pragma unroll
            for (int k = 0; k < 4; ++k) acc[i][k] = 0.0f;

        stage_h(0, 0, hbuf);

        for (int kc = 0; kc < NCHUNK; ++kc) {
            const int buf = kc & 1;
            cp_wait0();
            __syncthreads();
            if (kc + 1 < NCHUNK) stage_h(buf ^ 1, kc + 1, hbuf);

            const __half* th = ht[buf];

            // split-K: this warp covers k in [kgrp*128, kgrp*128+128) of the chunk
            #pragma unroll
            for (int ks = 0; ks < 8; ++ks) {
                const int kb = kgrp * 128 + ks * 16;
                unsigned ah[4], bh[4];
                ldsm_x4(ah, th + (wm * 16 + aRow) * (KC + HTPAD) + kb + aCol);
                const int koff = kc * KC + kb + bCol;
                ldsm_x4(bh, whhi + bRow * (Hsz + WPAD) + koff);
                mma16816h(acc[0], ah, bh);
                mma16816h(acc[1], ah, bh + 2);
            }
        }

        // partial gate pre-activations -> SMEM (un-scale 512 here).
        // No barrier needed before this write: the publish barrier of step t-1
        // already ordered the previous cell reads of gates0/gates1.
        const float IS = 1.0f / 512.0f;
        float* gp = kgrp ? gates1 : gates0;
        #pragma unroll
        for (int nt = 0; nt < 2; ++nt) {
            const int c = wn * 16 + nt * 8 + 2 * tg;
            const int r = wm * 16 + g;
            gp[r * NG + c]           = acc[nt][0] * IS;
            gp[r * NG + c + 1]       = acc[nt][1] * IS;
            gp[(r + 8) * NG + c]     = acc[nt][2] * IS;
            gp[(r + 8) * NG + c + 1] = acc[nt][3] * IS;
        }
        __syncthreads();

        // LSTM cell: 512 items, one per thread; reduce the two K-partials
        const int nb = (t + 1) % 3;
        {
            const int base = b_0 * NG + jj_0;
            const float pf = gates0[base]      + gates1[base]      + xp[0];
            const float pi = gates0[base + 8]  + gates1[base + 8]  + xp[1];
            const float pg = gates0[base + 16] + gates1[base + 16] + xp[2];
            const float po = gates0[base + 24] + gates1[base + 24] + xp[3];
            const float f = sigmoidf_(pf);
            const float ii = sigmoidf_(pi);
            const float gg = tanhf_(pg);
            const float o = sigmoidf_(po);
            c_reg = f * c_reg + ii * gg;
            const float h = o * tanhf_(c_reg);
            out[((size_t)b_0 * Lsz + t) * Hsz + j0 + jj_0] = h;
            g_hh3[nb][b_0 * Hsz + j0 + jj_0] = __float2half(h);
        }

        // publish: this block finished step t for its region
        __threadfence();
        __syncthreads();
        if (tid == 0) atomicAdd(&g_rc[region], 1u);

        // prefetch xproj for next step
        if (t + 1 < Lsz) {
            const size_t base0 = ((size_t)b_0 * Lsz + (t + 1)) * Gsz + j0 + jj_0;
            xp[0] = __ldg(g_xproj + base0);
            xp[1] = __ldg(g_xproj + base0 + 1024);
            xp[2] = __ldg(g_xproj + base0 + 2048);
            xp[3] = __ldg(g_xproj + base0 + 3072);
        }
    }

    // finals
    {
        const float hv0 = out[((size_t)b_0 * Lsz + (Lsz - 1)) * Hsz + j0 + jj_0];
        out[OUTN + (size_t)b_0 * Hsz + j0 + jj_0] = hv0;
        out[OUTN + (size_t)Bsz * Hsz + (size_t)b_0 * Hsz + j0 + jj_0] = c_reg;
    }
}

// ---------------- launcher ----------------
extern "C" void kernel_launch(void* const* d_in, const int* in_sizes, int n_in,
                              void* d_out, int out_size) {
    const float* x = (const float*)d_in[0];
    const float* W = (const float*)d_in[1];
    const float* b = (const float*)d_in[2];
    float* out = (float*)d_out;

    split_x_kernel<<<2048, 256>>>(x);
    split_w_kernel<<<1024, 256>>>(W);
    init_kernel<<<256, 256>>>();

    cudaFuncSetAttribute(xproj_kernel, cudaFuncAttributeMaxDynamicSharedMemorySize,
                         (int)P1_SMEM);
    dim3 g1(Gsz / P1_BN, ML / P1_BM);   // (32, 256)
    xproj_kernel<<<g1, 256, P1_SMEM>>>(b);

    cudaFuncSetAttribute(lstm_kernel, cudaFuncAttributeMaxDynamicSharedMemorySize,
                         (int)SMEM_P2);
    lstm_kernel<<<NBLK2, NTH2, SMEM_P2>>>(out);
}